// round 1
// baseline (speedup 1.0000x reference)
#include <cuda_runtime.h>

// reset_layer: x (16,2000,2000) f32, leftm (10,10), rightm (10,10), bs=10.
// No padding (2000 % 10 == 0).
// out[b, jH*200+hc, jW*200+wc] = x[b, jH*200+hc, jW*200+wc]
//   + sum_{iH,iW} rightm[iH,jH] * leftm[jW,iW] * x[b, iH*200+hc, iW*200+wc]
//
// Fused two-stage (20 FMA/element instead of 100):
//   stage1: Y[iH][jW] = sum_iW L[jW,iW] * X[iH][iW]   (per pixel)
//   stage2: Z[jH][jW] = X[jH][jW] + sum_iH R[iH,jH] * Y[iH][jW]
//
// Block = 320 threads (10 warps) x 128 pixels (4 consecutive pixels per thread,
// float4 everywhere). Warp s is iH=s in stage 1, jW=s in stage 2. Y staged in
// shared memory (51.2 KB). Matrix operands are uniform-broadcast LDS, amortized
// 4x by the float4 vectorization.

#define NBATCH   16
#define HPIX     2000
#define WPIX     2000
#define BSZ      10
#define HC       200        // HPIX / BSZ
#define WC       200        // WPIX / BSZ
#define PIX_TOTAL (NBATCH * HC * WC)      // 640000
#define PIX_PER_BLOCK 128
#define THREADS  320
#define SMEM_BYTES ((100 * PIX_PER_BLOCK + 200) * 4)   // Ys + L + R = 52000 B

extern "C" __global__ void __launch_bounds__(THREADS, 2)
reset_layer_kernel(const float* __restrict__ x,
                   const float* __restrict__ leftm,
                   const float* __restrict__ rightm,
                   float* __restrict__ out)
{
    extern __shared__ float smem[];
    float*  Ys  = smem;                       // [10][10][128] floats
    float*  Ls  = smem + 100 * PIX_PER_BLOCK; // [100]
    float*  Rs  = Ls + 100;                   // [100]
    float4* Ys4 = reinterpret_cast<float4*>(Ys);

    const int tid = threadIdx.x;
    const int s   = tid >> 5;   // warp id, 0..9 : role index (iH then jW)
    const int t   = tid & 31;   // lane: which pixel-quad in the tile

    if (tid < 100)       Ls[tid]       = leftm[tid];
    else if (tid < 200)  Rs[tid - 100] = rightm[tid - 100];

    // pixel-quad index (4 consecutive pixels; never crosses a wc chunk
    // boundary because wc = q mod 200 is a multiple of 4)
    const int q  = blockIdx.x * PIX_PER_BLOCK + t * 4;
    const int b  = q / (HC * WC);
    const int r  = q - b * (HC * WC);
    const int hc = r / WC;
    const int wc = r - hc * WC;

    __syncthreads();

    // ---------------- stage 1: this warp's iH = s ----------------
    // X row base for (b, iH=s, hc): element (b*2000 + s*200 + hc)*2000 + iW*200 + wc
    const float* xrow = x + (size_t)(b * HPIX + s * HC + hc) * WPIX + wc;

    float4 Xv[10];
#pragma unroll
    for (int iW = 0; iW < 10; iW++)
        Xv[iW] = *reinterpret_cast<const float4*>(xrow + iW * WC);

    float4 accY[10];
#pragma unroll
    for (int jW = 0; jW < 10; jW++)
        accY[jW] = make_float4(0.f, 0.f, 0.f, 0.f);

#pragma unroll
    for (int iW = 0; iW < 10; iW++) {
        const float4 xv = Xv[iW];
#pragma unroll
        for (int jW = 0; jW < 10; jW++) {
            const float l = Ls[jW * 10 + iW];
            accY[jW].x = fmaf(l, xv.x, accY[jW].x);
            accY[jW].y = fmaf(l, xv.y, accY[jW].y);
            accY[jW].z = fmaf(l, xv.z, accY[jW].z);
            accY[jW].w = fmaf(l, xv.w, accY[jW].w);
        }
    }

#pragma unroll
    for (int jW = 0; jW < 10; jW++)
        Ys4[(s * 10 + jW) * 32 + t] = accY[jW];

    __syncthreads();

    // ---------------- stage 2: this warp's jW = s ----------------
    // element (b*2000 + jH*200 + hc)*2000 + s*200 + wc
    const size_t base2 = (size_t)(b * HPIX + hc) * WPIX + s * WC + wc;

    float4 Z[10];
#pragma unroll
    for (int jH = 0; jH < 10; jH++)   // init with identity (L1 hit)
        Z[jH] = *reinterpret_cast<const float4*>(x + base2 + (size_t)jH * (HC * (size_t)WPIX));

#pragma unroll
    for (int iH = 0; iH < 10; iH++) {
        const float4 yv = Ys4[(iH * 10 + s) * 32 + t];
#pragma unroll
        for (int jH = 0; jH < 10; jH++) {
            const float rr = Rs[iH * 10 + jH];
            Z[jH].x = fmaf(rr, yv.x, Z[jH].x);
            Z[jH].y = fmaf(rr, yv.y, Z[jH].y);
            Z[jH].z = fmaf(rr, yv.z, Z[jH].z);
            Z[jH].w = fmaf(rr, yv.w, Z[jH].w);
        }
    }

#pragma unroll
    for (int jH = 0; jH < 10; jH++)
        *reinterpret_cast<float4*>(out + base2 + (size_t)jH * (HC * (size_t)WPIX)) = Z[jH];
}

extern "C" void kernel_launch(void* const* d_in, const int* in_sizes, int n_in,
                              void* d_out, int out_size)
{
    const float* x  = (const float*)d_in[0];
    const float* lm = (const float*)d_in[1];
    const float* rm = (const float*)d_in[2];
    float* out = (float*)d_out;

    cudaFuncSetAttribute(reset_layer_kernel,
                         cudaFuncAttributeMaxDynamicSharedMemorySize, SMEM_BYTES);

    const int grid = PIX_TOTAL / PIX_PER_BLOCK;   // 5000
    reset_layer_kernel<<<grid, THREADS, SMEM_BYTES>>>(x, lm, rm, out);
}

// round 2
// speedup vs baseline: 1.0532x; 1.0532x over previous
#include <cuda_runtime.h>

// reset_layer: x (16,2000,2000) f32, leftm (10,10), rightm (10,10), bs=10.
// No padding (2000 % 10 == 0).
// out[b, jH*200+hc, jW*200+wc] = x[b, jH*200+hc, jW*200+wc]
//   + sum_{iH,iW} rightm[iH,jH] * leftm[jW,iW] * x[b, iH*200+hc, iW*200+wc]
//
// Two-stage fused (20 FMA/element):
//   stage1: Y[iH][jW] = sum_iW L[jW,iW] * X[iH][iW]
//   stage2: Z[jH][jW] = X[jH][jW] + sum_iH R[iH,jH] * Y[iH][jW]
//
// R1 change vs R0: occupancy was the limiter (29%, reg-file bound at 96 regs).
// Now: 640 threads (20 warps, 2 warps per role), float2 per thread (2 pixels),
// low-register restructure (stream accY/Z instead of holding both operand and
// accumulator arrays). Target <=48 regs -> 2 blocks/SM -> 40 warps (62.5% occ).

#define NBATCH   16
#define HPIX     2000
#define WPIX     2000
#define HC       200
#define WC       200
#define PIX_TOTAL (NBATCH * HC * WC)      // 640000
#define PIX_PER_BLOCK 128                 // 64 float2-pairs
#define THREADS  640
#define SMEM_BYTES ((100 * PIX_PER_BLOCK + 200) * 4)   // 52000 B

extern "C" __global__ void __launch_bounds__(THREADS, 2)
reset_layer_kernel(const float* __restrict__ x,
                   const float* __restrict__ leftm,
                   const float* __restrict__ rightm,
                   float* __restrict__ out)
{
    extern __shared__ float smem[];
    float*  Ys  = smem;                       // [10][10][64] float2 = 51200 B
    float*  Ls  = smem + 100 * PIX_PER_BLOCK;
    float*  Rs  = Ls + 100;
    float2* Ys2 = reinterpret_cast<float2*>(Ys);

    const int tid  = threadIdx.x;
    const int w    = tid >> 5;
    const int lane = tid & 31;
    const int s    = w >> 1;                      // role 0..9 (iH then jW)
    const int t2   = ((w & 1) << 5) | lane;       // pixel-pair slot 0..63

    if (tid < 100)       Ls[tid]       = leftm[tid];
    else if (tid < 200)  Rs[tid - 100] = rightm[tid - 100];

    // pixel index (2 consecutive pixels per thread; wc stays even, never
    // crosses a 200-wide chunk boundary)
    const int p  = blockIdx.x * PIX_PER_BLOCK + t2 * 2;
    const int b  = p / (HC * WC);
    const int r  = p - b * (HC * WC);
    const int hc = r / WC;
    const int wc = r - hc * WC;

    __syncthreads();

    // ---------------- stage 1: this role's iH = s ----------------
    const float* xrow = x + (size_t)(b * HPIX + s * HC + hc) * WPIX + wc;

    float2 Xv[10];
#pragma unroll
    for (int iW = 0; iW < 10; iW++)
        Xv[iW] = *reinterpret_cast<const float2*>(xrow + iW * WC);

#pragma unroll
    for (int jW = 0; jW < 10; jW++) {
        float2 acc = make_float2(0.f, 0.f);
#pragma unroll
        for (int iW = 0; iW < 10; iW++) {
            const float l = Ls[jW * 10 + iW];
            acc.x = fmaf(l, Xv[iW].x, acc.x);
            acc.y = fmaf(l, Xv[iW].y, acc.y);
        }
        Ys2[(s * 10 + jW) * 64 + t2] = acc;
    }

    __syncthreads();

    // ---------------- stage 2: this role's jW = s ----------------
    float2 yv[10];
#pragma unroll
    for (int iH = 0; iH < 10; iH++)
        yv[iH] = Ys2[(iH * 10 + s) * 64 + t2];

    const size_t base2 = (size_t)(b * HPIX + hc) * WPIX + s * WC + wc;

#pragma unroll
    for (int jH = 0; jH < 10; jH++) {
        const size_t off = base2 + (size_t)jH * (HC * (size_t)WPIX);
        float2 z = *reinterpret_cast<const float2*>(x + off);   // identity (L1 hit)
#pragma unroll
        for (int iH = 0; iH < 10; iH++) {
            const float rr = Rs[iH * 10 + jH];
            z.x = fmaf(rr, yv[iH].x, z.x);
            z.y = fmaf(rr, yv[iH].y, z.y);
        }
        *reinterpret_cast<float2*>(out + off) = z;
    }
}

extern "C" void kernel_launch(void* const* d_in, const int* in_sizes, int n_in,
                              void* d_out, int out_size)
{
    const float* x  = (const float*)d_in[0];
    const float* lm = (const float*)d_in[1];
    const float* rm = (const float*)d_in[2];
    float* out = (float*)d_out;

    cudaFuncSetAttribute(reset_layer_kernel,
                         cudaFuncAttributeMaxDynamicSharedMemorySize, SMEM_BYTES);

    const int grid = PIX_TOTAL / PIX_PER_BLOCK;   // 5000
    reset_layer_kernel<<<grid, THREADS, SMEM_BYTES>>>(x, lm, rm, out);
}

// round 3
// speedup vs baseline: 1.1948x; 1.1344x over previous
#include <cuda_runtime.h>

// reset_layer: x (16,2000,2000) f32, leftm (10,10), rightm (10,10), bs=10.
// out[b, jH*200+hc, jW*200+wc] = x[...] + sum_{iH,iW} R[iH,jH]*L[jW,iW]*x[b, iH*200+hc, iW*200+wc]
//
// Two-stage fused (20 FMA/element):
//   stage1: Y[iH][jW] = sum_iW L[jW,iW] * X[iH][iW]
//   stage2: Z[jH][jW] = X[jH][jW] + sum_iH R[iH,jH] * Y[iH][jW]
//
// R2 change: matrices moved from shared memory to __constant__ memory.
// The 200 broadcast scalar LDS per thread were ~3/4 of the L1/MIO wavefront
// traffic (L1=68%, the hottest unit) and throttled the LDG stream (DRAM stuck
// at 55%). Constant-port loads (LDC/LDCU) use a separate path.

#define NBATCH   16
#define HPIX     2000
#define WPIX     2000
#define HC       200
#define WC       200
#define PIX_TOTAL (NBATCH * HC * WC)      // 640000
#define PIX_PER_BLOCK 128                 // 64 float2-pairs
#define THREADS  640
#define SMEM_BYTES (100 * PIX_PER_BLOCK * 4)   // Ys only: 51200 B

__constant__ float cL[100];
__constant__ float cR[100];

extern "C" __global__ void __launch_bounds__(THREADS, 2)
reset_layer_kernel(const float* __restrict__ x,
                   float* __restrict__ out)
{
    extern __shared__ float smem[];
    float2* Ys2 = reinterpret_cast<float2*>(smem);   // [10][10][64] float2

    const int tid  = threadIdx.x;
    const int w    = tid >> 5;
    const int lane = tid & 31;
    const int s    = w >> 1;                      // role 0..9 (iH then jW)
    const int t2   = ((w & 1) << 5) | lane;       // pixel-pair slot 0..63

    // pixel index (2 consecutive pixels per thread; wc stays even, never
    // crosses a 200-wide chunk boundary)
    const int p  = blockIdx.x * PIX_PER_BLOCK + t2 * 2;
    const int b  = p / (HC * WC);
    const int r  = p - b * (HC * WC);
    const int hc = r / WC;
    const int wc = r - hc * WC;

    // ---------------- stage 1: this role's iH = s ----------------
    const float* xrow = x + (size_t)(b * HPIX + s * HC + hc) * WPIX + wc;

    float2 Xv[10];
#pragma unroll
    for (int iW = 0; iW < 10; iW++)
        Xv[iW] = *reinterpret_cast<const float2*>(xrow + iW * WC);

#pragma unroll
    for (int jW = 0; jW < 10; jW++) {
        float2 acc = make_float2(0.f, 0.f);
#pragma unroll
        for (int iW = 0; iW < 10; iW++) {
            const float l = cL[jW * 10 + iW];
            acc.x = fmaf(l, Xv[iW].x, acc.x);
            acc.y = fmaf(l, Xv[iW].y, acc.y);
        }
        Ys2[(s * 10 + jW) * 64 + t2] = acc;
    }

    __syncthreads();

    // ---------------- stage 2: this role's jW = s ----------------
    float2 yv[10];
#pragma unroll
    for (int iH = 0; iH < 10; iH++)
        yv[iH] = Ys2[(iH * 10 + s) * 64 + t2];

    const size_t base2 = (size_t)(b * HPIX + hc) * WPIX + s * WC + wc;

#pragma unroll
    for (int jH = 0; jH < 10; jH++) {
        const size_t off = base2 + (size_t)jH * (HC * (size_t)WPIX);
        float2 z = *reinterpret_cast<const float2*>(x + off);   // identity (L1 hit)
#pragma unroll
        for (int iH = 0; iH < 10; iH++) {
            const float rr = cR[iH * 10 + jH];
            z.x = fmaf(rr, yv[iH].x, z.x);
            z.y = fmaf(rr, yv[iH].y, z.y);
        }
        *reinterpret_cast<float2*>(out + off) = z;
    }
}

extern "C" void kernel_launch(void* const* d_in, const int* in_sizes, int n_in,
                              void* d_out, int out_size)
{
    const float* x  = (const float*)d_in[0];
    const float* lm = (const float*)d_in[1];
    const float* rm = (const float*)d_in[2];
    float* out = (float*)d_out;

    // D2D memcpy nodes — graph-capturable, no allocation.
    cudaMemcpyToSymbolAsync(cL, lm, 100 * sizeof(float), 0,
                            cudaMemcpyDeviceToDevice, 0);
    cudaMemcpyToSymbolAsync(cR, rm, 100 * sizeof(float), 0,
                            cudaMemcpyDeviceToDevice, 0);

    cudaFuncSetAttribute(reset_layer_kernel,
                         cudaFuncAttributeMaxDynamicSharedMemorySize, SMEM_BYTES);

    const int grid = PIX_TOTAL / PIX_PER_BLOCK;   // 5000
    reset_layer_kernel<<<grid, THREADS, SMEM_BYTES>>>(x, out);
}